// round 9
// baseline (speedup 1.0000x reference)
#include <cuda_runtime.h>
#include <math.h>

// X is (65536, 512) fp32 row-major.
// Base: R6 kernel (best measured, 78.1us). Changes vs R6:
//  - stage2a+2b fused into one kernel via self-resetting last-block ticket
//  - pass1 partial writes use DEFAULT policy (stage rereads them immediately;
//    R6's __stcs on partials pushed them out of L2 before the reread)
#define CDIM 512
#define BDIM 65536
#define NB1  2048            // pass-1 blocks: 32 rows each -> 1 partial row
#define R1   (BDIM / NB1)    // 32 rows per block, 16 per parity
#define NB2  74              // stage blocks
#define NB3  2048            // pass-3 blocks (32 rows each)
#define R3   (BDIM / NB3)    // 32

// Static device scratch (no allocations allowed).
__device__ __align__(16) float g_sumP[NB1][CDIM];
__device__ __align__(16) float g_maxP[NB1][CDIM];
__device__ __align__(16) float g_minP[NB1][CDIM];
__device__ __align__(16) float g_sum2[NB2][CDIM];
__device__ __align__(16) float g_max2[NB2][CDIM];
__device__ __align__(16) float g_min2[NB2][CDIM];
__device__ __align__(16) float g_mean[CDIM];
__device__ __align__(16) float g_c1[CDIM];
__device__ __align__(16) float g_c2[CDIM];
__device__ __align__(16) float g_wc[CDIM];
__device__ float g_sn1;
// atomicInc with limit NB2-1 wraps to 0 after exactly NB2 increments ->
// self-resetting every launch (deterministic across graph replays).
__device__ unsigned int g_ticket = 0;

// ---------------------------------------------------------------------------
// Pass 1: per-column partial sum/max/min. Block b covers rows [b*32,(b+1)*32);
// 256 threads = 128 float4 column-groups x 2 row parities (16 rows each).
// Loads issued in explicit batches of 4 before accumulation (MLP >= 4).
// Default cache policy on X (pass3 harvests the L2-resident tail) AND on the
// partial writes (the stage kernel rereads them within ~2us).
// ---------------------------------------------------------------------------
__global__ void __launch_bounds__(256) k_pass1(const float* __restrict__ X) {
    const int tc = threadIdx.x & 127;   // column group 0..127
    const int tr = threadIdx.x >> 7;    // row parity 0..1
    const int b = blockIdx.x;
    const float4* Xp = reinterpret_cast<const float4*>(X);
    size_t base = ((size_t)b * R1 + tr) * (CDIM / 4) + tc;
    const size_t rs = CDIM / 4;         // float4 row stride

    float4 s  = make_float4(0.f, 0.f, 0.f, 0.f);
    float4 mx = make_float4(-INFINITY, -INFINITY, -INFINITY, -INFINITY);
    float4 mn = make_float4( INFINITY,  INFINITY,  INFINITY,  INFINITY);

#pragma unroll
    for (int rr = 0; rr < R1 / 2; rr += 4) {        // 16 rows per parity
        float4 v0 = Xp[base + (size_t)(2 * rr + 0) * rs];
        float4 v1 = Xp[base + (size_t)(2 * rr + 2) * rs];
        float4 v2 = Xp[base + (size_t)(2 * rr + 4) * rs];
        float4 v3 = Xp[base + (size_t)(2 * rr + 6) * rs];

        s.x += v0.x; s.y += v0.y; s.z += v0.z; s.w += v0.w;
        mx.x = fmaxf(mx.x, v0.x); mx.y = fmaxf(mx.y, v0.y);
        mx.z = fmaxf(mx.z, v0.z); mx.w = fmaxf(mx.w, v0.w);
        mn.x = fminf(mn.x, v0.x); mn.y = fminf(mn.y, v0.y);
        mn.z = fminf(mn.z, v0.z); mn.w = fminf(mn.w, v0.w);

        s.x += v1.x; s.y += v1.y; s.z += v1.z; s.w += v1.w;
        mx.x = fmaxf(mx.x, v1.x); mx.y = fmaxf(mx.y, v1.y);
        mx.z = fmaxf(mx.z, v1.z); mx.w = fmaxf(mx.w, v1.w);
        mn.x = fminf(mn.x, v1.x); mn.y = fminf(mn.y, v1.y);
        mn.z = fminf(mn.z, v1.z); mn.w = fminf(mn.w, v1.w);

        s.x += v2.x; s.y += v2.y; s.z += v2.z; s.w += v2.w;
        mx.x = fmaxf(mx.x, v2.x); mx.y = fmaxf(mx.y, v2.y);
        mx.z = fmaxf(mx.z, v2.z); mx.w = fmaxf(mx.w, v2.w);
        mn.x = fminf(mn.x, v2.x); mn.y = fminf(mn.y, v2.y);
        mn.z = fminf(mn.z, v2.z); mn.w = fminf(mn.w, v2.w);

        s.x += v3.x; s.y += v3.y; s.z += v3.z; s.w += v3.w;
        mx.x = fmaxf(mx.x, v3.x); mx.y = fmaxf(mx.y, v3.y);
        mx.z = fmaxf(mx.z, v3.z); mx.w = fmaxf(mx.w, v3.w);
        mn.x = fminf(mn.x, v3.x); mn.y = fminf(mn.y, v3.y);
        mn.z = fminf(mn.z, v3.z); mn.w = fminf(mn.w, v3.w);
    }

    __shared__ float4 shS[128], shA[128], shI[128];
    if (tr == 1) { shS[tc] = s; shA[tc] = mx; shI[tc] = mn; }
    __syncthreads();
    if (tr == 0) {
        float4 s2 = shS[tc], a2 = shA[tc], i2 = shI[tc];
        s.x += s2.x; s.y += s2.y; s.z += s2.z; s.w += s2.w;
        mx.x = fmaxf(mx.x, a2.x); mx.y = fmaxf(mx.y, a2.y);
        mx.z = fmaxf(mx.z, a2.z); mx.w = fmaxf(mx.w, a2.w);
        mn.x = fminf(mn.x, i2.x); mn.y = fminf(mn.y, i2.y);
        mn.z = fminf(mn.z, i2.z); mn.w = fminf(mn.w, i2.w);
        reinterpret_cast<float4*>(g_sumP[b])[tc] = s;
        reinterpret_cast<float4*>(g_maxP[b])[tc] = mx;
        reinterpret_cast<float4*>(g_minP[b])[tc] = mn;
    }
}

// ---------------------------------------------------------------------------
// Fused stage: 74 blocks x 512 threads. Block b reduces its proportional
// slice of the 2048 partial rows (whole-row reads: thread j owns column j ->
// fully coalesced 2 KiB transactions) into g_*2[b]. The LAST block to finish
// (self-resetting ticket) then reduces the 74 rows and computes mean/u/dev,
// SN1/SN2/SN3 and the fused per-column constants (old stage2b).
// Reduction order is fixed -> bitwise deterministic regardless of arrival
// order. Exactly NB2 atomicInc's per launch -> ticket returns to 0.
// ---------------------------------------------------------------------------
__device__ __forceinline__ float pow2_floor_log2(float v) {
    // replicates exp2(floor(log2(floor(v)))) including the v<1 -> 0 edge
    float f = floorf(v);
    if (f < 1.0f) return 0.0f;
    return ldexpf(1.0f, ilogbf(f));
}

__global__ void __launch_bounds__(512) k_stage(const float* __restrict__ w,
                                               const float* __restrict__ bia) {
    const int j = threadIdx.x;    // column 0..511
    const int b = blockIdx.x;     // 0..NB2-1
    const int r0 = (int)(((long long)b * NB1) / NB2);
    const int r1 = (int)(((long long)(b + 1) * NB1) / NB2);

    float s = 0.f, mx = -INFINITY, mn = INFINITY;
    for (int r = r0; r < r1; r++) {
        s += g_sumP[r][j];
        mx = fmaxf(mx, g_maxP[r][j]);
        mn = fminf(mn, g_minP[r][j]);
    }
    g_sum2[b][j] = s;
    g_max2[b][j] = mx;
    g_min2[b][j] = mn;

    // publish, then elect the last block
    __threadfence();
    __syncthreads();
    __shared__ unsigned int s_last;
    if (j == 0) {
        unsigned int old = atomicInc(&g_ticket, NB2 - 1);
        s_last = (old == NB2 - 1) ? 1u : 0u;
    }
    __syncthreads();
    if (!s_last) return;
    __threadfence();   // order the reads below after all blocks' writes

    // ---- final reduce over the 74 stage rows (fixed order) ----
    s = 0.f; mx = -INFINITY; mn = INFINITY;
#pragma unroll
    for (int r = 0; r < NB2; r++) {
        s += g_sum2[r][j];
        mx = fmaxf(mx, g_max2[r][j]);
        mn = fminf(mn, g_min2[r][j]);
    }
    const float cb = (float)(1.0 / sqrt(2.0 * log((double)BDIM)));
    float mean = s * (1.0f / (float)BDIM);     // /2^16: exact scaling
    float uv   = cb * (mx - mn);
    float dev  = fmaxf(mx - mean, mean - mn);  // = max_i |x[i,j]-mean_j|

    float wv = w[j];
    float bv = bia[j];

    __shared__ float sh[CDIM];
    __shared__ float s_dmax, s_wmax, s_sn1, s_sn2, s_sn3;

    // dmax = max over cols of max(|q|_col, |u|_col)
    sh[j] = fmaxf(dev, fabsf(uv));
    __syncthreads();
    for (int off = 256; off > 0; off >>= 1) {
        if (j < off) sh[j] = fmaxf(sh[j], sh[j + off]);
        __syncthreads();
    }
    if (j == 0) s_dmax = (sh[0] == 0.f) ? 1.f : sh[0];
    __syncthreads();

    sh[j] = fabsf(wv);
    __syncthreads();
    for (int off = 256; off > 0; off >>= 1) {
        if (j < off) sh[j] = fmaxf(sh[j], sh[j + off]);
        __syncthreads();
    }
    if (j == 0) s_wmax = (sh[0] == 0.f) ? 1.f : sh[0];
    __syncthreads();

    sh[j] = fabsf(bv);
    __syncthreads();
    for (int off = 256; off > 0; off >>= 1) {
        if (j < off) sh[j] = fmaxf(sh[j], sh[j + off]);
        __syncthreads();
    }
    if (j == 0) {
        float bmax = (sh[0] == 0.f) ? 1.f : sh[0];
        s_sn1 = pow2_floor_log2(32.0f / s_dmax);
        s_sn2 = pow2_floor_log2(32.0f / s_wmax);
        s_sn3 = pow2_floor_log2(32.0f / bmax);
        g_sn1 = s_sn1;
    }
    __syncthreads();

    const float SN1 = s_sn1, SN2 = s_sn2, SN3 = s_sn3;

    int uu = (int)(uv * SN1);       // trunc toward zero == astype(int32)
    int ww = (int)(wv * SN2);
    int bq = (int)(bv * SN3);

    int iu = min(abs(uu), 64);
    int ib = min(abs(bq), 64);
    float sgu = (uv > 0.f) ? 1.f : ((uv < 0.f) ? -1.f : 0.f);
    float sgb = (bv > 0.f) ? 1.f : ((bv < 0.f) ? -1.f : 0.f);
    float x8 = (float)(iu * ib) * sgu * sgb;

    float ssv = (float)uu * SN2 * SN3;
    g_mean[j] = mean;
    g_c1[j]   = SN3 / ssv;          // x7 coefficient
    g_c2[j]   = x8 * SN2 / ssv;     // additive term

    int wc = max(-64, min(64, ww)); // signed-clamp == sign*clip(|.|,64)
    g_wc[j] = (float)wc;
}

// ---------------------------------------------------------------------------
// Pass 3: elementwise output, reversed block order (first waves hit the
// still-L2-resident tail of X from pass1; and its own last-read region —
// X's beginning — is what pass1 of the NEXT graph replay reads first).
// X loads default policy; output stores __stcs so the written stream
// doesn't evict X. w-group g = row>>7 (repeat_interleave pairing:
// k//B == row>>7 exactly). out = clamp((int)((x-mean)*SN1),+-64)*(wc[g]*c1[j])+c2[j]
// ---------------------------------------------------------------------------
__global__ void __launch_bounds__(256) k_pass3(const float* __restrict__ X,
                                               float* __restrict__ O) {
    const int tc = threadIdx.x & 127;   // column group 0..127
    const int tr = threadIdx.x >> 7;    // row parity 0..1
    const int row0 = BDIM - (blockIdx.x + 1) * R3;   // reversed order
    const int g = row0 >> 7;            // 32-row blocks never straddle groups

    float4 m  = reinterpret_cast<const float4*>(g_mean)[tc];
    float4 c1 = reinterpret_cast<const float4*>(g_c1)[tc];
    float4 c2 = reinterpret_cast<const float4*>(g_c2)[tc];
    const float wg  = g_wc[g];
    const float sn1 = g_sn1;
    float4 e1;
    e1.x = wg * c1.x; e1.y = wg * c1.y; e1.z = wg * c1.z; e1.w = wg * c1.w;

    const float4* Xp = reinterpret_cast<const float4*>(X);
    float4* Op = reinterpret_cast<float4*>(O);
    size_t base = (size_t)(row0 + tr) * (CDIM / 4) + tc;

#pragma unroll 8
    for (int r = 0; r < R3; r += 2) {
        float4 v = Xp[base + (size_t)r * (CDIM / 4)];
        float4 o;
        {
            int q = (int)((v.x - m.x) * sn1);
            q = max(-64, min(64, q));
            o.x = (float)q * e1.x + c2.x;
        }
        {
            int q = (int)((v.y - m.y) * sn1);
            q = max(-64, min(64, q));
            o.y = (float)q * e1.y + c2.y;
        }
        {
            int q = (int)((v.z - m.z) * sn1);
            q = max(-64, min(64, q));
            o.z = (float)q * e1.z + c2.z;
        }
        {
            int q = (int)((v.w - m.w) * sn1);
            q = max(-64, min(64, q));
            o.w = (float)q * e1.w + c2.w;
        }
        __stcs(Op + base + (size_t)r * (CDIM / 4), o);
    }
}

// ---------------------------------------------------------------------------
extern "C" void kernel_launch(void* const* d_in, const int* in_sizes, int n_in,
                              void* d_out, int out_size) {
    const float* X  = (const float*)d_in[0];   // (65536, 512)
    const float* w  = (const float*)d_in[1];   // (512,)
    const float* bi = (const float*)d_in[2];   // (512,)
    float* O = (float*)d_out;

    k_pass1<<<NB1, 256>>>(X);
    k_stage<<<NB2, CDIM>>>(w, bi);
    k_pass3<<<NB3, 256>>>(X, O);
}

// round 10
// speedup vs baseline: 1.0743x; 1.0743x over previous
#include <cuda_runtime.h>
#include <math.h>

// X is (65536, 512) fp32 row-major.
// Base: R6 kernel (best measured, 78.1us; pass1 ~26us @5.4TB/s, pass3 ~40us).
// Single change vs R6: stage2a widened to 128 blocks x 256 threads with
// float4 reads (was 64 blocks x 512 threads, scalar). stage2b reduces 128
// rows instead of 64. Everything else byte-identical to R6.
#define CDIM 512
#define BDIM 65536
#define NB1  2048            // pass-1 blocks: 32 rows each -> 1 partial row
#define R1   (BDIM / NB1)    // 32 rows per block, 16 per parity
#define NB2  128             // stage-2a blocks: each reduces 16 partial rows
#define NB3  2048            // pass-3 blocks (32 rows each)
#define R3   (BDIM / NB3)    // 32

// Static device scratch (no allocations allowed).
__device__ __align__(16) float g_sumP[NB1][CDIM];
__device__ __align__(16) float g_maxP[NB1][CDIM];
__device__ __align__(16) float g_minP[NB1][CDIM];
__device__ __align__(16) float g_sum2[NB2][CDIM];
__device__ __align__(16) float g_max2[NB2][CDIM];
__device__ __align__(16) float g_min2[NB2][CDIM];
__device__ __align__(16) float g_mean[CDIM];
__device__ __align__(16) float g_c1[CDIM];
__device__ __align__(16) float g_c2[CDIM];
__device__ __align__(16) float g_wc[CDIM];
__device__ float g_sn1;

// ---------------------------------------------------------------------------
// Pass 1: per-column partial sum/max/min. Block b covers rows [b*32,(b+1)*32);
// 256 threads = 128 float4 column-groups x 2 row parities (16 rows each).
// Loads issued in explicit batches of 4 before accumulation (MLP >= 4) —
// measured 25.9us @ 5.42TB/s in R9. Default cache policy on X (pass3
// harvests the L2-resident tail); partials via __stcs (R6 config).
// ---------------------------------------------------------------------------
__global__ void __launch_bounds__(256) k_pass1(const float* __restrict__ X) {
    const int tc = threadIdx.x & 127;   // column group 0..127
    const int tr = threadIdx.x >> 7;    // row parity 0..1
    const int b = blockIdx.x;
    const float4* Xp = reinterpret_cast<const float4*>(X);
    size_t base = ((size_t)b * R1 + tr) * (CDIM / 4) + tc;
    const size_t rs = CDIM / 4;         // float4 row stride

    float4 s  = make_float4(0.f, 0.f, 0.f, 0.f);
    float4 mx = make_float4(-INFINITY, -INFINITY, -INFINITY, -INFINITY);
    float4 mn = make_float4( INFINITY,  INFINITY,  INFINITY,  INFINITY);

#pragma unroll
    for (int rr = 0; rr < R1 / 2; rr += 4) {        // 16 rows per parity
        float4 v0 = Xp[base + (size_t)(2 * rr + 0) * rs];
        float4 v1 = Xp[base + (size_t)(2 * rr + 2) * rs];
        float4 v2 = Xp[base + (size_t)(2 * rr + 4) * rs];
        float4 v3 = Xp[base + (size_t)(2 * rr + 6) * rs];

        s.x += v0.x; s.y += v0.y; s.z += v0.z; s.w += v0.w;
        mx.x = fmaxf(mx.x, v0.x); mx.y = fmaxf(mx.y, v0.y);
        mx.z = fmaxf(mx.z, v0.z); mx.w = fmaxf(mx.w, v0.w);
        mn.x = fminf(mn.x, v0.x); mn.y = fminf(mn.y, v0.y);
        mn.z = fminf(mn.z, v0.z); mn.w = fminf(mn.w, v0.w);

        s.x += v1.x; s.y += v1.y; s.z += v1.z; s.w += v1.w;
        mx.x = fmaxf(mx.x, v1.x); mx.y = fmaxf(mx.y, v1.y);
        mx.z = fmaxf(mx.z, v1.z); mx.w = fmaxf(mx.w, v1.w);
        mn.x = fminf(mn.x, v1.x); mn.y = fminf(mn.y, v1.y);
        mn.z = fminf(mn.z, v1.z); mn.w = fminf(mn.w, v1.w);

        s.x += v2.x; s.y += v2.y; s.z += v2.z; s.w += v2.w;
        mx.x = fmaxf(mx.x, v2.x); mx.y = fmaxf(mx.y, v2.y);
        mx.z = fmaxf(mx.z, v2.z); mx.w = fmaxf(mx.w, v2.w);
        mn.x = fminf(mn.x, v2.x); mn.y = fminf(mn.y, v2.y);
        mn.z = fminf(mn.z, v2.z); mn.w = fminf(mn.w, v2.w);

        s.x += v3.x; s.y += v3.y; s.z += v3.z; s.w += v3.w;
        mx.x = fmaxf(mx.x, v3.x); mx.y = fmaxf(mx.y, v3.y);
        mx.z = fmaxf(mx.z, v3.z); mx.w = fmaxf(mx.w, v3.w);
        mn.x = fminf(mn.x, v3.x); mn.y = fminf(mn.y, v3.y);
        mn.z = fminf(mn.z, v3.z); mn.w = fminf(mn.w, v3.w);
    }

    __shared__ float4 shS[128], shA[128], shI[128];
    if (tr == 1) { shS[tc] = s; shA[tc] = mx; shI[tc] = mn; }
    __syncthreads();
    if (tr == 0) {
        float4 s2 = shS[tc], a2 = shA[tc], i2 = shI[tc];
        s.x += s2.x; s.y += s2.y; s.z += s2.z; s.w += s2.w;
        mx.x = fmaxf(mx.x, a2.x); mx.y = fmaxf(mx.y, a2.y);
        mx.z = fmaxf(mx.z, a2.z); mx.w = fmaxf(mx.w, a2.w);
        mn.x = fminf(mn.x, i2.x); mn.y = fminf(mn.y, i2.y);
        mn.z = fminf(mn.z, i2.z); mn.w = fminf(mn.w, i2.w);
        __stcs(reinterpret_cast<float4*>(g_sumP[b]) + tc, s);
        __stcs(reinterpret_cast<float4*>(g_maxP[b]) + tc, mx);
        __stcs(reinterpret_cast<float4*>(g_minP[b]) + tc, mn);
    }
}

// ---------------------------------------------------------------------------
// Stage 2a: 128 blocks x 256 threads, float4 reads. Block b reduces whole
// partial rows [b*16, b*16+16): 128 column-groups x 2 row parities (8 rows
// each), parity-combined via smem. Each row read = fully coalesced float4
// transactions. Emits one row per block.
// ---------------------------------------------------------------------------
__global__ void __launch_bounds__(256) k_stage2a() {
    const int tc = threadIdx.x & 127;   // column group 0..127
    const int tr = threadIdx.x >> 7;    // row parity 0..1
    const int b = blockIdx.x;           // 0..127
    const int r0 = b * (NB1 / NB2);     // 16 rows each

    float4 s  = make_float4(0.f, 0.f, 0.f, 0.f);
    float4 mx = make_float4(-INFINITY, -INFINITY, -INFINITY, -INFINITY);
    float4 mn = make_float4( INFINITY,  INFINITY,  INFINITY,  INFINITY);

#pragma unroll
    for (int r = tr; r < NB1 / NB2; r += 2) {
        float4 vs = reinterpret_cast<const float4*>(g_sumP[r0 + r])[tc];
        float4 va = reinterpret_cast<const float4*>(g_maxP[r0 + r])[tc];
        float4 vi = reinterpret_cast<const float4*>(g_minP[r0 + r])[tc];
        s.x += vs.x; s.y += vs.y; s.z += vs.z; s.w += vs.w;
        mx.x = fmaxf(mx.x, va.x); mx.y = fmaxf(mx.y, va.y);
        mx.z = fmaxf(mx.z, va.z); mx.w = fmaxf(mx.w, va.w);
        mn.x = fminf(mn.x, vi.x); mn.y = fminf(mn.y, vi.y);
        mn.z = fminf(mn.z, vi.z); mn.w = fminf(mn.w, vi.w);
    }

    __shared__ float4 shS[128], shA[128], shI[128];
    if (tr == 1) { shS[tc] = s; shA[tc] = mx; shI[tc] = mn; }
    __syncthreads();
    if (tr == 0) {
        float4 s2 = shS[tc], a2 = shA[tc], i2 = shI[tc];
        s.x += s2.x; s.y += s2.y; s.z += s2.z; s.w += s2.w;
        mx.x = fmaxf(mx.x, a2.x); mx.y = fmaxf(mx.y, a2.y);
        mx.z = fmaxf(mx.z, a2.z); mx.w = fmaxf(mx.w, a2.w);
        mn.x = fminf(mn.x, i2.x); mn.y = fminf(mn.y, i2.y);
        mn.z = fminf(mn.z, i2.z); mn.w = fminf(mn.w, i2.w);
        reinterpret_cast<float4*>(g_sum2[b])[tc] = s;
        reinterpret_cast<float4*>(g_max2[b])[tc] = mx;
        reinterpret_cast<float4*>(g_min2[b])[tc] = mn;
    }
}

// ---------------------------------------------------------------------------
// Stage 2b: one block, 512 threads. Finishes the 128-row reduce per column,
// computes mean/u/dev, three global maxima -> SN1/SN2/SN3, and the fused
// per-column constants for pass3.
// ---------------------------------------------------------------------------
__device__ __forceinline__ float pow2_floor_log2(float v) {
    // replicates exp2(floor(log2(floor(v)))) including the v<1 -> 0 edge
    float f = floorf(v);
    if (f < 1.0f) return 0.0f;
    return ldexpf(1.0f, ilogbf(f));
}

__global__ void k_stage2b(const float* __restrict__ w,
                          const float* __restrict__ bia) {
    const int j = threadIdx.x;  // 0..511

    float s = 0.f, mx = -INFINITY, mn = INFINITY;
#pragma unroll 16
    for (int r = 0; r < NB2; r++) {
        s += g_sum2[r][j];
        mx = fmaxf(mx, g_max2[r][j]);
        mn = fminf(mn, g_min2[r][j]);
    }
    const float cb = (float)(1.0 / sqrt(2.0 * log((double)BDIM)));
    float mean = s * (1.0f / (float)BDIM);     // /2^16: exact scaling
    float uv   = cb * (mx - mn);
    float dev  = fmaxf(mx - mean, mean - mn);  // = max_i |x[i,j]-mean_j|

    float wv = w[j];
    float bv = bia[j];

    __shared__ float sh[CDIM];
    __shared__ float s_dmax, s_wmax, s_sn1, s_sn2, s_sn3;

    // dmax = max over cols of max(|q|_col, |u|_col)
    sh[j] = fmaxf(dev, fabsf(uv));
    __syncthreads();
    for (int off = 256; off > 0; off >>= 1) {
        if (j < off) sh[j] = fmaxf(sh[j], sh[j + off]);
        __syncthreads();
    }
    if (j == 0) s_dmax = (sh[0] == 0.f) ? 1.f : sh[0];
    __syncthreads();

    sh[j] = fabsf(wv);
    __syncthreads();
    for (int off = 256; off > 0; off >>= 1) {
        if (j < off) sh[j] = fmaxf(sh[j], sh[j + off]);
        __syncthreads();
    }
    if (j == 0) s_wmax = (sh[0] == 0.f) ? 1.f : sh[0];
    __syncthreads();

    sh[j] = fabsf(bv);
    __syncthreads();
    for (int off = 256; off > 0; off >>= 1) {
        if (j < off) sh[j] = fmaxf(sh[j], sh[j + off]);
        __syncthreads();
    }
    if (j == 0) {
        float bmax = (sh[0] == 0.f) ? 1.f : sh[0];
        s_sn1 = pow2_floor_log2(32.0f / s_dmax);
        s_sn2 = pow2_floor_log2(32.0f / s_wmax);
        s_sn3 = pow2_floor_log2(32.0f / bmax);
        g_sn1 = s_sn1;
    }
    __syncthreads();

    const float SN1 = s_sn1, SN2 = s_sn2, SN3 = s_sn3;

    int uu = (int)(uv * SN1);       // trunc toward zero == astype(int32)
    int ww = (int)(wv * SN2);
    int bq = (int)(bv * SN3);

    int iu = min(abs(uu), 64);
    int ib = min(abs(bq), 64);
    float sgu = (uv > 0.f) ? 1.f : ((uv < 0.f) ? -1.f : 0.f);
    float sgb = (bv > 0.f) ? 1.f : ((bv < 0.f) ? -1.f : 0.f);
    float x8 = (float)(iu * ib) * sgu * sgb;

    float ssv = (float)uu * SN2 * SN3;
    g_mean[j] = mean;
    g_c1[j]   = SN3 / ssv;          // x7 coefficient
    g_c2[j]   = x8 * SN2 / ssv;     // additive term

    int wc = max(-64, min(64, ww)); // signed-clamp == sign*clip(|.|,64)
    g_wc[j] = (float)wc;
}

// ---------------------------------------------------------------------------
// Pass 3: elementwise output, reversed block order (first waves hit the
// still-L2-resident tail of X from pass1). X loads default policy; output
// stores __stcs so the written stream doesn't evict X. w-group g = row>>7
// (repeat_interleave pairing: k//B == row>>7 exactly).
// out = clamp((int)((x-mean)*SN1), +-64) * (wc[g]*c1[j]) + c2[j]
// ---------------------------------------------------------------------------
__global__ void __launch_bounds__(256) k_pass3(const float* __restrict__ X,
                                               float* __restrict__ O) {
    const int tc = threadIdx.x & 127;   // column group 0..127
    const int tr = threadIdx.x >> 7;    // row parity 0..1
    const int row0 = BDIM - (blockIdx.x + 1) * R3;   // reversed order
    const int g = row0 >> 7;            // 32-row blocks never straddle groups

    float4 m  = reinterpret_cast<const float4*>(g_mean)[tc];
    float4 c1 = reinterpret_cast<const float4*>(g_c1)[tc];
    float4 c2 = reinterpret_cast<const float4*>(g_c2)[tc];
    const float wg  = g_wc[g];
    const float sn1 = g_sn1;
    float4 e1;
    e1.x = wg * c1.x; e1.y = wg * c1.y; e1.z = wg * c1.z; e1.w = wg * c1.w;

    const float4* Xp = reinterpret_cast<const float4*>(X);
    float4* Op = reinterpret_cast<float4*>(O);
    size_t base = (size_t)(row0 + tr) * (CDIM / 4) + tc;

#pragma unroll 8
    for (int r = 0; r < R3; r += 2) {
        float4 v = Xp[base + (size_t)r * (CDIM / 4)];
        float4 o;
        {
            int q = (int)((v.x - m.x) * sn1);
            q = max(-64, min(64, q));
            o.x = (float)q * e1.x + c2.x;
        }
        {
            int q = (int)((v.y - m.y) * sn1);
            q = max(-64, min(64, q));
            o.y = (float)q * e1.y + c2.y;
        }
        {
            int q = (int)((v.z - m.z) * sn1);
            q = max(-64, min(64, q));
            o.z = (float)q * e1.z + c2.z;
        }
        {
            int q = (int)((v.w - m.w) * sn1);
            q = max(-64, min(64, q));
            o.w = (float)q * e1.w + c2.w;
        }
        __stcs(Op + base + (size_t)r * (CDIM / 4), o);
    }
}

// ---------------------------------------------------------------------------
extern "C" void kernel_launch(void* const* d_in, const int* in_sizes, int n_in,
                              void* d_out, int out_size) {
    const float* X  = (const float*)d_in[0];   // (65536, 512)
    const float* w  = (const float*)d_in[1];   // (512,)
    const float* bi = (const float*)d_in[2];   // (512,)
    float* O = (float*)d_out;

    k_pass1<<<NB1, 256>>>(X);
    k_stage2a<<<NB2, 256>>>();
    k_stage2b<<<1, CDIM>>>(w, bi);
    k_pass3<<<NB3, 256>>>(X, O);
}

// round 13
// speedup vs baseline: 1.0773x; 1.0028x over previous
#include <cuda_runtime.h>
#include <math.h>

// X is (65536, 512) fp32 row-major.
// PDL ABANDONED: the R11 PDL kernel killed the container twice in a row
// (device-side hang signature), unlike all prior one-off infra flakes.
// This is the R6 record config (78.1us measured) with ONE micro change:
// stage2a reads the (single-use) partials with __ldcs so they evict first,
// preserving more of X's tail in L2 for reversed-order pass3.
#define CDIM 512
#define BDIM 65536
#define NB1  2048            // pass-1 blocks: 32 rows each -> 1 partial row
#define R1   (BDIM / NB1)    // 32 rows per block, 16 per parity
#define NB2  64              // stage-2a blocks: each reduces 32 partial rows
#define NB3  2048            // pass-3 blocks (32 rows each)
#define R3   (BDIM / NB3)    // 32

// Static device scratch (no allocations allowed).
__device__ __align__(16) float g_sumP[NB1][CDIM];
__device__ __align__(16) float g_maxP[NB1][CDIM];
__device__ __align__(16) float g_minP[NB1][CDIM];
__device__ __align__(16) float g_sum2[NB2][CDIM];
__device__ __align__(16) float g_max2[NB2][CDIM];
__device__ __align__(16) float g_min2[NB2][CDIM];
__device__ __align__(16) float g_mean[CDIM];
__device__ __align__(16) float g_c1[CDIM];
__device__ __align__(16) float g_c2[CDIM];
__device__ __align__(16) float g_wc[CDIM];
__device__ float g_sn1;

// ---------------------------------------------------------------------------
// Pass 1: per-column partial sum/max/min. Block b covers rows [b*32,(b+1)*32);
// 256 threads = 128 float4 column-groups x 2 row parities (16 rows each).
// Loads issued in explicit batches of 4 before accumulation (MLP >= 4;
// measured 25.9us @ 5.42TB/s). Default cache policy on X (pass3 harvests the
// L2-resident tail); partial writes __stcs (R6 config).
// ---------------------------------------------------------------------------
__global__ void __launch_bounds__(256) k_pass1(const float* __restrict__ X) {
    const int tc = threadIdx.x & 127;   // column group 0..127
    const int tr = threadIdx.x >> 7;    // row parity 0..1
    const int b = blockIdx.x;
    const float4* Xp = reinterpret_cast<const float4*>(X);
    size_t base = ((size_t)b * R1 + tr) * (CDIM / 4) + tc;
    const size_t rs = CDIM / 4;         // float4 row stride

    float4 s  = make_float4(0.f, 0.f, 0.f, 0.f);
    float4 mx = make_float4(-INFINITY, -INFINITY, -INFINITY, -INFINITY);
    float4 mn = make_float4( INFINITY,  INFINITY,  INFINITY,  INFINITY);

#pragma unroll
    for (int rr = 0; rr < R1 / 2; rr += 4) {        // 16 rows per parity
        float4 v0 = Xp[base + (size_t)(2 * rr + 0) * rs];
        float4 v1 = Xp[base + (size_t)(2 * rr + 2) * rs];
        float4 v2 = Xp[base + (size_t)(2 * rr + 4) * rs];
        float4 v3 = Xp[base + (size_t)(2 * rr + 6) * rs];

        s.x += v0.x; s.y += v0.y; s.z += v0.z; s.w += v0.w;
        mx.x = fmaxf(mx.x, v0.x); mx.y = fmaxf(mx.y, v0.y);
        mx.z = fmaxf(mx.z, v0.z); mx.w = fmaxf(mx.w, v0.w);
        mn.x = fminf(mn.x, v0.x); mn.y = fminf(mn.y, v0.y);
        mn.z = fminf(mn.z, v0.z); mn.w = fminf(mn.w, v0.w);

        s.x += v1.x; s.y += v1.y; s.z += v1.z; s.w += v1.w;
        mx.x = fmaxf(mx.x, v1.x); mx.y = fmaxf(mx.y, v1.y);
        mx.z = fmaxf(mx.z, v1.z); mx.w = fmaxf(mx.w, v1.w);
        mn.x = fminf(mn.x, v1.x); mn.y = fminf(mn.y, v1.y);
        mn.z = fminf(mn.z, v1.z); mn.w = fminf(mn.w, v1.w);

        s.x += v2.x; s.y += v2.y; s.z += v2.z; s.w += v2.w;
        mx.x = fmaxf(mx.x, v2.x); mx.y = fmaxf(mx.y, v2.y);
        mx.z = fmaxf(mx.z, v2.z); mx.w = fmaxf(mx.w, v2.w);
        mn.x = fminf(mn.x, v2.x); mn.y = fminf(mn.y, v2.y);
        mn.z = fminf(mn.z, v2.z); mn.w = fminf(mn.w, v2.w);

        s.x += v3.x; s.y += v3.y; s.z += v3.z; s.w += v3.w;
        mx.x = fmaxf(mx.x, v3.x); mx.y = fmaxf(mx.y, v3.y);
        mx.z = fmaxf(mx.z, v3.z); mx.w = fmaxf(mx.w, v3.w);
        mn.x = fminf(mn.x, v3.x); mn.y = fminf(mn.y, v3.y);
        mn.z = fminf(mn.z, v3.z); mn.w = fminf(mn.w, v3.w);
    }

    __shared__ float4 shS[128], shA[128], shI[128];
    if (tr == 1) { shS[tc] = s; shA[tc] = mx; shI[tc] = mn; }
    __syncthreads();
    if (tr == 0) {
        float4 s2 = shS[tc], a2 = shA[tc], i2 = shI[tc];
        s.x += s2.x; s.y += s2.y; s.z += s2.z; s.w += s2.w;
        mx.x = fmaxf(mx.x, a2.x); mx.y = fmaxf(mx.y, a2.y);
        mx.z = fmaxf(mx.z, a2.z); mx.w = fmaxf(mx.w, a2.w);
        mn.x = fminf(mn.x, i2.x); mn.y = fminf(mn.y, i2.y);
        mn.z = fminf(mn.z, i2.z); mn.w = fminf(mn.w, i2.w);
        __stcs(reinterpret_cast<float4*>(g_sumP[b]) + tc, s);
        __stcs(reinterpret_cast<float4*>(g_maxP[b]) + tc, mx);
        __stcs(reinterpret_cast<float4*>(g_minP[b]) + tc, mn);
    }
}

// ---------------------------------------------------------------------------
// Stage 2a: 64 blocks x 512 threads. Block b reduces whole partial rows
// [b*32, b*32+32): thread j owns column j -> fully coalesced 2 KiB row
// reads. Partials are single-use -> __ldcs (evict-first) so they don't
// occupy L2 that pass3 wants for X. Emits one row per block.
// ---------------------------------------------------------------------------
__global__ void k_stage2a() {
    const int j = threadIdx.x;    // column 0..511
    const int b = blockIdx.x;     // 0..63
    const int r0 = b * (NB1 / NB2);   // 32 rows each

    float s = 0.f, mx = -INFINITY, mn = INFINITY;
#pragma unroll 8
    for (int r = 0; r < NB1 / NB2; r++) {
        s += __ldcs(&g_sumP[r0 + r][j]);
        mx = fmaxf(mx, __ldcs(&g_maxP[r0 + r][j]));
        mn = fminf(mn, __ldcs(&g_minP[r0 + r][j]));
    }
    g_sum2[b][j] = s;
    g_max2[b][j] = mx;
    g_min2[b][j] = mn;
}

// ---------------------------------------------------------------------------
// Stage 2b: one block, 512 threads. Finishes the 64-row reduce per column,
// computes mean/u/dev, three global maxima -> SN1/SN2/SN3, and the fused
// per-column constants for pass3.
// ---------------------------------------------------------------------------
__device__ __forceinline__ float pow2_floor_log2(float v) {
    // replicates exp2(floor(log2(floor(v)))) including the v<1 -> 0 edge
    float f = floorf(v);
    if (f < 1.0f) return 0.0f;
    return ldexpf(1.0f, ilogbf(f));
}

__global__ void k_stage2b(const float* __restrict__ w,
                          const float* __restrict__ bia) {
    const int j = threadIdx.x;  // 0..511

    float s = 0.f, mx = -INFINITY, mn = INFINITY;
#pragma unroll
    for (int r = 0; r < NB2; r++) {
        s += g_sum2[r][j];
        mx = fmaxf(mx, g_max2[r][j]);
        mn = fminf(mn, g_min2[r][j]);
    }
    const float cb = (float)(1.0 / sqrt(2.0 * log((double)BDIM)));
    float mean = s * (1.0f / (float)BDIM);     // /2^16: exact scaling
    float uv   = cb * (mx - mn);
    float dev  = fmaxf(mx - mean, mean - mn);  // = max_i |x[i,j]-mean_j|

    float wv = w[j];
    float bv = bia[j];

    __shared__ float sh[CDIM];
    __shared__ float s_dmax, s_wmax, s_sn1, s_sn2, s_sn3;

    // dmax = max over cols of max(|q|_col, |u|_col)
    sh[j] = fmaxf(dev, fabsf(uv));
    __syncthreads();
    for (int off = 256; off > 0; off >>= 1) {
        if (j < off) sh[j] = fmaxf(sh[j], sh[j + off]);
        __syncthreads();
    }
    if (j == 0) s_dmax = (sh[0] == 0.f) ? 1.f : sh[0];
    __syncthreads();

    sh[j] = fabsf(wv);
    __syncthreads();
    for (int off = 256; off > 0; off >>= 1) {
        if (j < off) sh[j] = fmaxf(sh[j], sh[j + off]);
        __syncthreads();
    }
    if (j == 0) s_wmax = (sh[0] == 0.f) ? 1.f : sh[0];
    __syncthreads();

    sh[j] = fabsf(bv);
    __syncthreads();
    for (int off = 256; off > 0; off >>= 1) {
        if (j < off) sh[j] = fmaxf(sh[j], sh[j + off]);
        __syncthreads();
    }
    if (j == 0) {
        float bmax = (sh[0] == 0.f) ? 1.f : sh[0];
        s_sn1 = pow2_floor_log2(32.0f / s_dmax);
        s_sn2 = pow2_floor_log2(32.0f / s_wmax);
        s_sn3 = pow2_floor_log2(32.0f / bmax);
        g_sn1 = s_sn1;
    }
    __syncthreads();

    const float SN1 = s_sn1, SN2 = s_sn2, SN3 = s_sn3;

    int uu = (int)(uv * SN1);       // trunc toward zero == astype(int32)
    int ww = (int)(wv * SN2);
    int bq = (int)(bv * SN3);

    int iu = min(abs(uu), 64);
    int ib = min(abs(bq), 64);
    float sgu = (uv > 0.f) ? 1.f : ((uv < 0.f) ? -1.f : 0.f);
    float sgb = (bv > 0.f) ? 1.f : ((bv < 0.f) ? -1.f : 0.f);
    float x8 = (float)(iu * ib) * sgu * sgb;

    float ssv = (float)uu * SN2 * SN3;
    g_mean[j] = mean;
    g_c1[j]   = SN3 / ssv;          // x7 coefficient
    g_c2[j]   = x8 * SN2 / ssv;     // additive term

    int wc = max(-64, min(64, ww)); // signed-clamp == sign*clip(|.|,64)
    g_wc[j] = (float)wc;
}

// ---------------------------------------------------------------------------
// Pass 3: elementwise output, reversed block order (first waves hit the
// still-L2-resident tail of X from pass1). X loads default policy; output
// stores __stcs so the written stream doesn't evict X. w-group g = row>>7
// (repeat_interleave pairing: k//B == row>>7 exactly).
// out = clamp((int)((x-mean)*SN1), +-64) * (wc[g]*c1[j]) + c2[j]
// ---------------------------------------------------------------------------
__global__ void __launch_bounds__(256) k_pass3(const float* __restrict__ X,
                                               float* __restrict__ O) {
    const int tc = threadIdx.x & 127;   // column group 0..127
    const int tr = threadIdx.x >> 7;    // row parity 0..1
    const int row0 = BDIM - (blockIdx.x + 1) * R3;   // reversed order
    const int g = row0 >> 7;            // 32-row blocks never straddle groups

    float4 m  = reinterpret_cast<const float4*>(g_mean)[tc];
    float4 c1 = reinterpret_cast<const float4*>(g_c1)[tc];
    float4 c2 = reinterpret_cast<const float4*>(g_c2)[tc];
    const float wg  = g_wc[g];
    const float sn1 = g_sn1;
    float4 e1;
    e1.x = wg * c1.x; e1.y = wg * c1.y; e1.z = wg * c1.z; e1.w = wg * c1.w;

    const float4* Xp = reinterpret_cast<const float4*>(X);
    float4* Op = reinterpret_cast<float4*>(O);
    size_t base = (size_t)(row0 + tr) * (CDIM / 4) + tc;

#pragma unroll 8
    for (int r = 0; r < R3; r += 2) {
        float4 v = Xp[base + (size_t)r * (CDIM / 4)];
        float4 o;
        {
            int q = (int)((v.x - m.x) * sn1);
            q = max(-64, min(64, q));
            o.x = (float)q * e1.x + c2.x;
        }
        {
            int q = (int)((v.y - m.y) * sn1);
            q = max(-64, min(64, q));
            o.y = (float)q * e1.y + c2.y;
        }
        {
            int q = (int)((v.z - m.z) * sn1);
            q = max(-64, min(64, q));
            o.z = (float)q * e1.z + c2.z;
        }
        {
            int q = (int)((v.w - m.w) * sn1);
            q = max(-64, min(64, q));
            o.w = (float)q * e1.w + c2.w;
        }
        __stcs(Op + base + (size_t)r * (CDIM / 4), o);
    }
}

// ---------------------------------------------------------------------------
extern "C" void kernel_launch(void* const* d_in, const int* in_sizes, int n_in,
                              void* d_out, int out_size) {
    const float* X  = (const float*)d_in[0];   // (65536, 512)
    const float* w  = (const float*)d_in[1];   // (512,)
    const float* bi = (const float*)d_in[2];   // (512,)
    float* O = (float*)d_out;

    k_pass1<<<NB1, 256>>>(X);
    k_stage2a<<<NB2, CDIM>>>();
    k_stage2b<<<1, CDIM>>>(w, bi);
    k_pass3<<<NB3, 256>>>(X, O);
}

// round 15
// speedup vs baseline: 1.0913x; 1.0130x over previous
#include <cuda_runtime.h>
#include <math.h>

// X is (65536, 512) fp32 row-major.
// RECORD CONFIG (R6, measured 78.1us) verbatim. R14's bench of this exact
// source died with the recurring container infra error — which, since this
// source ALREADY PASSED in R6, proves the failure mode is infra-side and
// content-independent. Resubmitting for the plateau-confirmation number.
// pass1: 2048x256, batched-4 loads, __stcs partials (25.9us @5.42TB/s meas.)
// stage2a: 64x512 scalar whole-row reads; stage2b: 1x512 finisher
// pass3: 2048x256 reversed order, default X loads, __stcs output (~40us)
// Rejected by measurement: persistent wave (R8), fused stage (R9), wide
// stage2a (R10), PDL (R11/12, unmeasurable), ldcs variants (R4, R13).
#define CDIM 512
#define BDIM 65536
#define NB1  2048            // pass-1 blocks: 32 rows each -> 1 partial row
#define R1   (BDIM / NB1)    // 32 rows per block, 16 per parity
#define NB2  64              // stage-2a blocks: each reduces 32 partial rows
#define NB3  2048            // pass-3 blocks (32 rows each)
#define R3   (BDIM / NB3)    // 32

// Static device scratch (no allocations allowed).
__device__ __align__(16) float g_sumP[NB1][CDIM];
__device__ __align__(16) float g_maxP[NB1][CDIM];
__device__ __align__(16) float g_minP[NB1][CDIM];
__device__ __align__(16) float g_sum2[NB2][CDIM];
__device__ __align__(16) float g_max2[NB2][CDIM];
__device__ __align__(16) float g_min2[NB2][CDIM];
__device__ __align__(16) float g_mean[CDIM];
__device__ __align__(16) float g_c1[CDIM];
__device__ __align__(16) float g_c2[CDIM];
__device__ __align__(16) float g_wc[CDIM];
__device__ float g_sn1;

// ---------------------------------------------------------------------------
// Pass 1: per-column partial sum/max/min. Block b covers rows [b*32,(b+1)*32);
// 256 threads = 128 float4 column-groups x 2 row parities (16 rows each).
// Loads issued in explicit batches of 4 before accumulation (MLP >= 4).
// Default cache policy on X (pass3 harvests the L2-resident tail);
// partial writes __stcs so they don't evict X.
// ---------------------------------------------------------------------------
__global__ void __launch_bounds__(256) k_pass1(const float* __restrict__ X) {
    const int tc = threadIdx.x & 127;   // column group 0..127
    const int tr = threadIdx.x >> 7;    // row parity 0..1
    const int b = blockIdx.x;
    const float4* Xp = reinterpret_cast<const float4*>(X);
    size_t base = ((size_t)b * R1 + tr) * (CDIM / 4) + tc;
    const size_t rs = CDIM / 4;         // float4 row stride

    float4 s  = make_float4(0.f, 0.f, 0.f, 0.f);
    float4 mx = make_float4(-INFINITY, -INFINITY, -INFINITY, -INFINITY);
    float4 mn = make_float4( INFINITY,  INFINITY,  INFINITY,  INFINITY);

#pragma unroll
    for (int rr = 0; rr < R1 / 2; rr += 4) {        // 16 rows per parity
        float4 v0 = Xp[base + (size_t)(2 * rr + 0) * rs];
        float4 v1 = Xp[base + (size_t)(2 * rr + 2) * rs];
        float4 v2 = Xp[base + (size_t)(2 * rr + 4) * rs];
        float4 v3 = Xp[base + (size_t)(2 * rr + 6) * rs];

        s.x += v0.x; s.y += v0.y; s.z += v0.z; s.w += v0.w;
        mx.x = fmaxf(mx.x, v0.x); mx.y = fmaxf(mx.y, v0.y);
        mx.z = fmaxf(mx.z, v0.z); mx.w = fmaxf(mx.w, v0.w);
        mn.x = fminf(mn.x, v0.x); mn.y = fminf(mn.y, v0.y);
        mn.z = fminf(mn.z, v0.z); mn.w = fminf(mn.w, v0.w);

        s.x += v1.x; s.y += v1.y; s.z += v1.z; s.w += v1.w;
        mx.x = fmaxf(mx.x, v1.x); mx.y = fmaxf(mx.y, v1.y);
        mx.z = fmaxf(mx.z, v1.z); mx.w = fmaxf(mx.w, v1.w);
        mn.x = fminf(mn.x, v1.x); mn.y = fminf(mn.y, v1.y);
        mn.z = fminf(mn.z, v1.z); mn.w = fminf(mn.w, v1.w);

        s.x += v2.x; s.y += v2.y; s.z += v2.z; s.w += v2.w;
        mx.x = fmaxf(mx.x, v2.x); mx.y = fmaxf(mx.y, v2.y);
        mx.z = fmaxf(mx.z, v2.z); mx.w = fmaxf(mx.w, v2.w);
        mn.x = fminf(mn.x, v2.x); mn.y = fminf(mn.y, v2.y);
        mn.z = fminf(mn.z, v2.z); mn.w = fminf(mn.w, v2.w);

        s.x += v3.x; s.y += v3.y; s.z += v3.z; s.w += v3.w;
        mx.x = fmaxf(mx.x, v3.x); mx.y = fmaxf(mx.y, v3.y);
        mx.z = fmaxf(mx.z, v3.z); mx.w = fmaxf(mx.w, v3.w);
        mn.x = fminf(mn.x, v3.x); mn.y = fminf(mn.y, v3.y);
        mn.z = fminf(mn.z, v3.z); mn.w = fminf(mn.w, v3.w);
    }

    __shared__ float4 shS[128], shA[128], shI[128];
    if (tr == 1) { shS[tc] = s; shA[tc] = mx; shI[tc] = mn; }
    __syncthreads();
    if (tr == 0) {
        float4 s2 = shS[tc], a2 = shA[tc], i2 = shI[tc];
        s.x += s2.x; s.y += s2.y; s.z += s2.z; s.w += s2.w;
        mx.x = fmaxf(mx.x, a2.x); mx.y = fmaxf(mx.y, a2.y);
        mx.z = fmaxf(mx.z, a2.z); mx.w = fmaxf(mx.w, a2.w);
        mn.x = fminf(mn.x, i2.x); mn.y = fminf(mn.y, i2.y);
        mn.z = fminf(mn.z, i2.z); mn.w = fminf(mn.w, i2.w);
        __stcs(reinterpret_cast<float4*>(g_sumP[b]) + tc, s);
        __stcs(reinterpret_cast<float4*>(g_maxP[b]) + tc, mx);
        __stcs(reinterpret_cast<float4*>(g_minP[b]) + tc, mn);
    }
}

// ---------------------------------------------------------------------------
// Stage 2a: 64 blocks x 512 threads. Block b reduces whole partial rows
// [b*32, b*32+32): thread j owns column j -> fully coalesced 2 KiB row
// reads. Emits one row per block.
// ---------------------------------------------------------------------------
__global__ void k_stage2a() {
    const int j = threadIdx.x;    // column 0..511
    const int b = blockIdx.x;     // 0..63
    const int r0 = b * (NB1 / NB2);   // 32 rows each

    float s = 0.f, mx = -INFINITY, mn = INFINITY;
#pragma unroll 8
    for (int r = 0; r < NB1 / NB2; r++) {
        s += g_sumP[r0 + r][j];
        mx = fmaxf(mx, g_maxP[r0 + r][j]);
        mn = fminf(mn, g_minP[r0 + r][j]);
    }
    g_sum2[b][j] = s;
    g_max2[b][j] = mx;
    g_min2[b][j] = mn;
}

// ---------------------------------------------------------------------------
// Stage 2b: one block, 512 threads. Finishes the 64-row reduce per column,
// computes mean/u/dev, three global maxima -> SN1/SN2/SN3, and the fused
// per-column constants for pass3.
// ---------------------------------------------------------------------------
__device__ __forceinline__ float pow2_floor_log2(float v) {
    // replicates exp2(floor(log2(floor(v)))) including the v<1 -> 0 edge
    float f = floorf(v);
    if (f < 1.0f) return 0.0f;
    return ldexpf(1.0f, ilogbf(f));
}

__global__ void k_stage2b(const float* __restrict__ w,
                          const float* __restrict__ bia) {
    const int j = threadIdx.x;  // 0..511

    float s = 0.f, mx = -INFINITY, mn = INFINITY;
#pragma unroll
    for (int r = 0; r < NB2; r++) {
        s += g_sum2[r][j];
        mx = fmaxf(mx, g_max2[r][j]);
        mn = fminf(mn, g_min2[r][j]);
    }
    const float cb = (float)(1.0 / sqrt(2.0 * log((double)BDIM)));
    float mean = s * (1.0f / (float)BDIM);     // /2^16: exact scaling
    float uv   = cb * (mx - mn);
    float dev  = fmaxf(mx - mean, mean - mn);  // = max_i |x[i,j]-mean_j|

    float wv = w[j];
    float bv = bia[j];

    __shared__ float sh[CDIM];
    __shared__ float s_dmax, s_wmax, s_sn1, s_sn2, s_sn3;

    // dmax = max over cols of max(|q|_col, |u|_col)
    sh[j] = fmaxf(dev, fabsf(uv));
    __syncthreads();
    for (int off = 256; off > 0; off >>= 1) {
        if (j < off) sh[j] = fmaxf(sh[j], sh[j + off]);
        __syncthreads();
    }
    if (j == 0) s_dmax = (sh[0] == 0.f) ? 1.f : sh[0];
    __syncthreads();

    sh[j] = fabsf(wv);
    __syncthreads();
    for (int off = 256; off > 0; off >>= 1) {
        if (j < off) sh[j] = fmaxf(sh[j], sh[j + off]);
        __syncthreads();
    }
    if (j == 0) s_wmax = (sh[0] == 0.f) ? 1.f : sh[0];
    __syncthreads();

    sh[j] = fabsf(bv);
    __syncthreads();
    for (int off = 256; off > 0; off >>= 1) {
        if (j < off) sh[j] = fmaxf(sh[j], sh[j + off]);
        __syncthreads();
    }
    if (j == 0) {
        float bmax = (sh[0] == 0.f) ? 1.f : sh[0];
        s_sn1 = pow2_floor_log2(32.0f / s_dmax);
        s_sn2 = pow2_floor_log2(32.0f / s_wmax);
        s_sn3 = pow2_floor_log2(32.0f / bmax);
        g_sn1 = s_sn1;
    }
    __syncthreads();

    const float SN1 = s_sn1, SN2 = s_sn2, SN3 = s_sn3;

    int uu = (int)(uv * SN1);       // trunc toward zero == astype(int32)
    int ww = (int)(wv * SN2);
    int bq = (int)(bv * SN3);

    int iu = min(abs(uu), 64);
    int ib = min(abs(bq), 64);
    float sgu = (uv > 0.f) ? 1.f : ((uv < 0.f) ? -1.f : 0.f);
    float sgb = (bv > 0.f) ? 1.f : ((bv < 0.f) ? -1.f : 0.f);
    float x8 = (float)(iu * ib) * sgu * sgb;

    float ssv = (float)uu * SN2 * SN3;
    g_mean[j] = mean;
    g_c1[j]   = SN3 / ssv;          // x7 coefficient
    g_c2[j]   = x8 * SN2 / ssv;     // additive term

    int wc = max(-64, min(64, ww)); // signed-clamp == sign*clip(|.|,64)
    g_wc[j] = (float)wc;
}

// ---------------------------------------------------------------------------
// Pass 3: elementwise output, reversed block order (first waves hit the
// still-L2-resident tail of X from pass1). X loads default policy; output
// stores __stcs so the written stream doesn't evict X. w-group g = row>>7
// (repeat_interleave pairing: k//B == row>>7 exactly).
// out = clamp((int)((x-mean)*SN1), +-64) * (wc[g]*c1[j]) + c2[j]
// ---------------------------------------------------------------------------
__global__ void __launch_bounds__(256) k_pass3(const float* __restrict__ X,
                                               float* __restrict__ O) {
    const int tc = threadIdx.x & 127;   // column group 0..127
    const int tr = threadIdx.x >> 7;    // row parity 0..1
    const int row0 = BDIM - (blockIdx.x + 1) * R3;   // reversed order
    const int g = row0 >> 7;            // 32-row blocks never straddle groups

    float4 m  = reinterpret_cast<const float4*>(g_mean)[tc];
    float4 c1 = reinterpret_cast<const float4*>(g_c1)[tc];
    float4 c2 = reinterpret_cast<const float4*>(g_c2)[tc];
    const float wg  = g_wc[g];
    const float sn1 = g_sn1;
    float4 e1;
    e1.x = wg * c1.x; e1.y = wg * c1.y; e1.z = wg * c1.z; e1.w = wg * c1.w;

    const float4* Xp = reinterpret_cast<const float4*>(X);
    float4* Op = reinterpret_cast<float4*>(O);
    size_t base = (size_t)(row0 + tr) * (CDIM / 4) + tc;

#pragma unroll 8
    for (int r = 0; r < R3; r += 2) {
        float4 v = Xp[base + (size_t)r * (CDIM / 4)];
        float4 o;
        {
            int q = (int)((v.x - m.x) * sn1);
            q = max(-64, min(64, q));
            o.x = (float)q * e1.x + c2.x;
        }
        {
            int q = (int)((v.y - m.y) * sn1);
            q = max(-64, min(64, q));
            o.y = (float)q * e1.y + c2.y;
        }
        {
            int q = (int)((v.z - m.z) * sn1);
            q = max(-64, min(64, q));
            o.z = (float)q * e1.z + c2.z;
        }
        {
            int q = (int)((v.w - m.w) * sn1);
            q = max(-64, min(64, q));
            o.w = (float)q * e1.w + c2.w;
        }
        __stcs(Op + base + (size_t)r * (CDIM / 4), o);
    }
}

// ---------------------------------------------------------------------------
extern "C" void kernel_launch(void* const* d_in, const int* in_sizes, int n_in,
                              void* d_out, int out_size) {
    const float* X  = (const float*)d_in[0];   // (65536, 512)
    const float* w  = (const float*)d_in[1];   // (512,)
    const float* bi = (const float*)d_in[2];   // (512,)
    float* O = (float*)d_out;

    k_pass1<<<NB1, 256>>>(X);
    k_stage2a<<<NB2, CDIM>>>();
    k_stage2b<<<1, CDIM>>>(w, bi);
    k_pass3<<<NB3, 256>>>(X, O);
}